// round 1
// baseline (speedup 1.0000x reference)
#include <cuda_runtime.h>
#include <math.h>

#define TOPK 13
#define EPSF 1e-7f
#define MAX_BN (1 << 20)
#define MAX_B 64

__device__ unsigned long long g_key[MAX_BN];
__device__ double g_acc[MAX_B * 8];

__device__ __forceinline__ float iou_fn(float4 a, float4 b) {
    float x1 = fmaxf(a.x, b.x), y1 = fmaxf(a.y, b.y);
    float x2 = fminf(a.z, b.z), y2 = fminf(a.w, b.w);
    float inter = fmaxf(x2 - x1, 0.0f) * fmaxf(y2 - y1, 0.0f);
    float aa = (a.z - a.x) * (a.w - a.y);
    float ab = (b.z - b.x) * (b.w - b.y);
    return inter / (aa + ab - inter + EPSF);
}

__global__ void k_zero(int total) {
    int i = blockIdx.x * blockDim.x + threadIdx.x;
    if (i < total) g_key[i] = 0ULL;
    if (i < MAX_B * 8) g_acc[i] = 0.0;
}

// One block per (image, gt). Compute align over all anchors, top-13, scatter keys.
__global__ __launch_bounds__(256) void k_assign(
    const float4* __restrict__ pred_boxes, const float* __restrict__ scores,
    const float2* __restrict__ anchors, const float4* __restrict__ gts,
    int B, int N, int G)
{
    int bg = blockIdx.x;
    int b = bg / G, g = bg % G;
    float4 gt = gts[bg];
    int t = threadIdx.x;

    float v[TOPK]; int id[TOPK];
#pragma unroll
    for (int j = 0; j < TOPK; j++) { v[j] = -1e30f; id[j] = 0x7FFFFFFF; }

    const float4* pb_b = pred_boxes + (size_t)b * N;
    const float*  sc_b = scores + (size_t)b * N;

    for (int a = t; a < N; a += 256) {
        float2 an = anchors[a];
        float align = -1.0f;
        if (an.x >= gt.x && an.x <= gt.z && an.y >= gt.y && an.y <= gt.w) {
            float4 pb = pb_b[a];
            float iou = iou_fn(pb, gt);
            float s = sc_b[a];
            float prob = 1.0f / (1.0f + expf(-s));
            float i2 = iou * iou;
            align = prob * (i2 * i2 * i2);
        }
        if (align > v[TOPK - 1]) {
            float cv = align; int ci = a;
#pragma unroll
            for (int j = 0; j < TOPK; j++) {
                if (cv > v[j]) {
                    float tv = v[j]; v[j] = cv; cv = tv;
                    int ti = id[j]; id[j] = ci; ci = ti;
                }
            }
        }
    }

    __shared__ float sv[256 * TOPK];
    __shared__ int   si[256 * TOPK];
    __shared__ float rv[256];
    __shared__ int   ri[256];
    __shared__ int   rp[256];
    __shared__ int   s_done;

#pragma unroll
    for (int j = 0; j < TOPK; j++) { sv[t * TOPK + j] = v[j]; si[t * TOPK + j] = id[j]; }
    if (t == 0) s_done = 0;
    __syncthreads();

    unsigned long long* keyb = g_key + (size_t)b * N;
    for (int round = 0; round < TOPK; round++) {
        float bv = -1e30f; int bi = 0x7FFFFFFF; int bp = -1;
        for (int p = t; p < 256 * TOPK; p += 256) {
            float cv = sv[p];
            int ci = si[p];
            if (cv > bv || (cv == bv && ci < bi)) { bv = cv; bi = ci; bp = p; }
        }
        rv[t] = bv; ri[t] = bi; rp[t] = bp;
        __syncthreads();
        for (int off = 128; off > 0; off >>= 1) {
            if (t < off) {
                if (rv[t + off] > rv[t] || (rv[t + off] == rv[t] && ri[t + off] < ri[t])) {
                    rv[t] = rv[t + off]; ri[t] = ri[t + off]; rp[t] = rp[t + off];
                }
            }
            __syncthreads();
        }
        if (t == 0) {
            float wv = rv[0];
            if (wv < 0.0f) {
                s_done = 1;   // remaining rounds are all negative -> never foreground
            } else {
                sv[rp[0]] = -1e30f;
                unsigned int bits = __float_as_uint(wv);
                unsigned long long key = (((unsigned long long)(bits + 1u)) << 32)
                                       | (unsigned long long)(0xFFFFFFFFu - (unsigned)g);
                atomicMax(&keyb[ri[0]], key);
            }
        }
        __syncthreads();
        if (s_done) break;
    }
}

// One thread per anchor: BCE for all, full loss terms for foreground only.
__global__ __launch_bounds__(256) void k_loss(
    const float4* __restrict__ pred_boxes, const float* __restrict__ scores,
    const float2* __restrict__ anchors, const float* __restrict__ strides,
    const float* __restrict__ logits, const float* __restrict__ prompt,
    const float4* __restrict__ gts, const int* __restrict__ img_p,
    int B, int N, int G, int P)
{
    int b = blockIdx.y;
    int a = blockIdx.x * blockDim.x + threadIdx.x;
    int t = threadIdx.x;

    float vals[8];
#pragma unroll
    for (int q = 0; q < 8; q++) vals[q] = 0.0f;

    if (a < N) {
        size_t idx = (size_t)b * N + a;
        float s = scores[idx];
        float prob = 1.0f / (1.0f + expf(-s));
        vals[3] = prob;                          // total prob sum
        unsigned long long key = g_key[idx];
        float ts = 0.0f;
        if (key != 0ULL) {
            int g = (int)(0xFFFFFFFFu - (unsigned)(key & 0xFFFFFFFFull));
            float4 gt = gts[b * G + g];
            float4 pb = pred_boxes[idx];
            float iou = iou_fn(pb, gt);
            ts = fmaxf(iou, 0.1f);
            vals[1] = 1.0f;                      // n_pos
            vals[2] = prob;                      // pos prob sum
            vals[4] = iou;                       // matched iou sum
            // CIoU
            float cw = fmaxf(pb.z, gt.z) - fminf(pb.x, gt.x);
            float ch = fmaxf(pb.w, gt.w) - fminf(pb.y, gt.y);
            float c2 = cw * cw + ch * ch + EPSF;
            float dx = gt.x + gt.z - pb.x - pb.z;
            float dy = gt.y + gt.w - pb.y - pb.w;
            float rho2 = (dx * dx + dy * dy) * 0.25f;
            float w1 = pb.z - pb.x, h1 = pb.w - pb.y + EPSF;
            float w2 = gt.z - gt.x, h2 = gt.w - gt.y + EPSF;
            float dat = atanf(w2 / h2) - atanf(w1 / h1);
            float vv = 0.40528473456935109f * dat * dat;   // 4/pi^2
            float alpha = vv / (vv - iou + 1.0f + EPSF);
            float ciou = iou - rho2 / c2 - vv * alpha;
            vals[5] = 1.0f - ciou;               // iou loss term
            // DFL
            float2 an = anchors[a];
            float st = strides[a];
            float dist[4];
            dist[0] = (an.x - gt.x) / st;
            dist[1] = (an.y - gt.y) / st;
            dist[2] = (gt.z - an.x) / st;
            dist[3] = (gt.w - an.y) / st;
            const float* lg = logits + idx * 64;
            float dflv = 0.0f;
#pragma unroll
            for (int ch_i = 0; ch_i < 4; ch_i++) {
                float x[16];
                const float4* l4 = (const float4*)(lg + ch_i * 16);
#pragma unroll
                for (int q = 0; q < 4; q++) {
                    float4 f = l4[q];
                    x[q * 4 + 0] = f.x; x[q * 4 + 1] = f.y;
                    x[q * 4 + 2] = f.z; x[q * 4 + 3] = f.w;
                }
                float m = x[0];
#pragma unroll
                for (int q = 1; q < 16; q++) m = fmaxf(m, x[q]);
                float se = 0.0f;
#pragma unroll
                for (int q = 0; q < 16; q++) se += expf(x[q] - m);
                float logZ = m + logf(se);
                float d = fminf(fmaxf(dist[ch_i], 0.0f), 16.0f - 1.0f - 0.01f);
                int tl = (int)d;
                int tr = min(tl + 1, 15);
                float wl = (float)tr - d;
                float wr = 1.0f - wl;
                dflv += (logZ - x[tl]) * wl + (logZ - x[tr]) * wr;
            }
            vals[6] = dflv;
            // contrast
            float img = fmaxf((float)img_p[0], 1.0f);
            float cx = (gt.x + gt.z) * 0.5f / img;
            float cy = (gt.y + gt.w) * 0.5f / img;
            float cn = fmaxf(sqrtf(cx * cx + cy * cy), 1e-12f);
            cx /= cn; cy /= cn;
            float p0 = prompt[(size_t)b * P + 0], p1 = prompt[(size_t)b * P + 1];
            float pn = fmaxf(sqrtf(p0 * p0 + p1 * p1), 1e-12f);
            vals[7] = 1.0f - (cx * p0 + cy * p1) / pn;
        }
        vals[0] = fmaxf(s, 0.0f) - s * ts + log1pf(expf(-fabsf(s)));  // BCE
    }

    __shared__ float red[256];
    for (int q = 0; q < 8; q++) {
        red[t] = vals[q];
        __syncthreads();
        for (int off = 128; off > 0; off >>= 1) {
            if (t < off) red[t] += red[t + off];
            __syncthreads();
        }
        if (t == 0 && red[0] != 0.0f) atomicAdd(&g_acc[b * 8 + q], (double)red[0]);
        __syncthreads();
    }
}

__global__ void k_final(float* __restrict__ out, int B, int N) {
    if (threadIdx.x != 0 || blockIdx.x != 0) return;
    double match = 0, iou = 0, dfl = 0, ctr = 0;
    double tp = 0, pos = 0, tot = 0, mi = 0;
    for (int b = 0; b < B; b++) {
        const double* A = &g_acc[b * 8];
        double np = A[1];
        double den = fmax(np, 1.0);
        match += A[0] / (double)N;
        tp += np;
        pos += A[2];
        tot += A[3];
        mi += A[4];
        iou += A[5] / den;
        dfl += A[6] / (4.0 * den);
        ctr += A[7] / den;
    }
    double nb = (double)B;
    double tneg = (double)B * (double)N - tp;
    out[0] = (float)((1.0 * match + 7.5 * iou + 1.5 * dfl + 1.0 * ctr) / nb);
    out[1] = (float)(match / nb);
    out[2] = (float)(iou / nb);
    out[3] = (float)(dfl / nb);
    out[4] = (float)(ctr / nb);
    out[5] = (float)tp;
    out[6] = (float)tneg;
    out[7] = (float)(pos / fmax(tp, 1.0));
    out[8] = (float)((tot - pos) / fmax(tneg, 1.0));
    out[9] = (float)(mi / fmax(tp, 1.0));
}

extern "C" void kernel_launch(void* const* d_in, const int* in_sizes, int n_in,
                              void* d_out, int out_size) {
    const float* pred_boxes = (const float*)d_in[0];
    const float* pred_scores = (const float*)d_in[1];
    const float* anchors = (const float*)d_in[2];
    const float* strides = (const float*)d_in[3];
    const float* logits = (const float*)d_in[4];
    const float* prompt = (const float*)d_in[5];
    const float* gts = (const float*)d_in[6];
    const int* imgp = (const int*)d_in[7];

    int N = in_sizes[2] / 2;
    int B = in_sizes[1] / N;
    int G = in_sizes[6] / (4 * B);
    int P = in_sizes[5] / B;
    int BN = B * N;

    k_zero<<<(BN + 255) / 256, 256>>>(BN);
    k_assign<<<B * G, 256>>>((const float4*)pred_boxes, pred_scores,
                             (const float2*)anchors, (const float4*)gts, B, N, G);
    dim3 g2((N + 255) / 256, (unsigned)B);
    k_loss<<<g2, 256>>>((const float4*)pred_boxes, pred_scores,
                        (const float2*)anchors, strides, logits, prompt,
                        (const float4*)gts, imgp, B, N, G, P);
    k_final<<<1, 32>>>((float*)d_out, B, N);
}

// round 2
// speedup vs baseline: 1.6649x; 1.6649x over previous
#include <cuda_runtime.h>
#include <math.h>
#include <float.h>

#define TOPK 13
#define EPSF 1e-7f
#define MAX_BN (1 << 20)
#define MAX_B 64
#define MAX_LIST 32768

__device__ unsigned long long g_key[MAX_BN];
__device__ double g_acc[MAX_B * 8];
__device__ int g_cnt;
__device__ int2 g_list[MAX_LIST];

__device__ __forceinline__ float iou_fn(float4 a, float4 b) {
    float x1 = fmaxf(a.x, b.x), y1 = fmaxf(a.y, b.y);
    float x2 = fminf(a.z, b.z), y2 = fminf(a.w, b.w);
    float inter = fmaxf(x2 - x1, 0.0f) * fmaxf(y2 - y1, 0.0f);
    float aa = (a.z - a.x) * (a.w - a.y);
    float ab = (b.z - b.x) * (b.w - b.y);
    return inter / (aa + ab - inter + EPSF);
}

// Dense, assignment-independent part: bce0 sum and prob sum per image.
__global__ __launch_bounds__(256) void k_score(
    const float* __restrict__ scores, int B, int N)
{
    int b = blockIdx.y;
    int base = (blockIdx.x * 256 + threadIdx.x) * 4;
    const float* sc = scores + (size_t)b * N;
    float bce0 = 0.0f, psum = 0.0f;
    if (base + 3 < N) {
        float4 s4 = *(const float4*)(sc + base);
        float ss[4] = {s4.x, s4.y, s4.z, s4.w};
#pragma unroll
        for (int j = 0; j < 4; j++) {
            float s = ss[j];
            bce0 += fmaxf(s, 0.0f) + log1pf(expf(-fabsf(s)));
            psum += 1.0f / (1.0f + expf(-s));
        }
    } else {
        for (int j = 0; j < 4; j++) {
            int i = base + j;
            if (i < N) {
                float s = sc[i];
                bce0 += fmaxf(s, 0.0f) + log1pf(expf(-fabsf(s)));
                psum += 1.0f / (1.0f + expf(-s));
            }
        }
    }
    // block reduce 2 values
    __shared__ float r0[8], r1[8];
    int lane = threadIdx.x & 31, wid = threadIdx.x >> 5;
#pragma unroll
    for (int off = 16; off > 0; off >>= 1) {
        bce0 += __shfl_down_sync(0xFFFFFFFFu, bce0, off);
        psum += __shfl_down_sync(0xFFFFFFFFu, psum, off);
    }
    if (lane == 0) { r0[wid] = bce0; r1[wid] = psum; }
    __syncthreads();
    if (threadIdx.x == 0) {
        float a = 0.0f, p = 0.0f;
        for (int w = 0; w < 8; w++) { a += r0[w]; p += r1[w]; }
        atomicAdd(&g_acc[b * 8 + 0], (double)a);
        atomicAdd(&g_acc[b * 8 + 3], (double)p);
    }
}

// One block (128 threads) per (image, gt). Candidate-range enumeration + top-13.
__global__ __launch_bounds__(128) void k_assign(
    const float4* __restrict__ pred_boxes, const float* __restrict__ scores,
    const float2* __restrict__ anchors, const float4* __restrict__ gts,
    const int* __restrict__ img_p, int B, int N, int G)
{
    int bg = blockIdx.x;
    int b = bg / G, g = bg % G;
    float4 gt = gts[bg];
    int t = threadIdx.x;

    float v[TOPK]; int id[TOPK];
#pragma unroll
    for (int j = 0; j < TOPK; j++) { v[j] = -FLT_MAX; id[j] = 0x7FFFFFFF; }

    const float4* pb_b = pred_boxes + (size_t)b * N;
    const float*  sc_b = scores + (size_t)b * N;

    int img = img_p[0];
    int n0 = img / 8, n1 = img / 16, n2 = img / 32;
    bool structured = (n0 * n0 + n1 * n1 + n2 * n2 == N) && img > 0;

    if (structured) {
        int nn[3] = {n0, n1, n2};
        int base[3] = {0, n0 * n0, n0 * n0 + n1 * n1};
        int c0[3], r0[3], cw[3], m[3];
        int M = 0;
#pragma unroll
        for (int sc = 0; sc < 3; sc++) {
            float s = (float)(8 << sc);
            int n = nn[sc];
            int cl = (int)floorf(gt.x / s - 0.5f) - 1;
            int ch = (int)ceilf(gt.z / s - 0.5f) + 1;
            int rl = (int)floorf(gt.y / s - 0.5f) - 1;
            int rh = (int)ceilf(gt.w / s - 0.5f) + 1;
            cl = max(cl, 0); ch = min(ch, n - 1);
            rl = max(rl, 0); rh = min(rh, n - 1);
            int ccw = ch - cl + 1, crh = rh - rl + 1;
            if (ccw < 0) ccw = 0;
            if (crh < 0) crh = 0;
            c0[sc] = cl; r0[sc] = rl; cw[sc] = ccw;
            m[sc] = ccw * crh;
            M += m[sc];
        }
        for (int k = t; k < M; k += 128) {
            int sc = 0, rel = k;
            while (rel >= m[sc]) { rel -= m[sc]; sc++; }
            int row = rel / cw[sc] + r0[sc];
            int col = rel % cw[sc] + c0[sc];
            int a = base[sc] + row * nn[sc] + col;
            float2 an = anchors[a];
            if (an.x >= gt.x && an.x <= gt.z && an.y >= gt.y && an.y <= gt.w) {
                float4 pb = pb_b[a];
                float iou = iou_fn(pb, gt);
                float s = sc_b[a];
                float prob = 1.0f / (1.0f + expf(-s));
                float i2 = iou * iou;
                float align = prob * (i2 * i2 * i2);
                if (align > v[TOPK - 1]) {
                    float cv = align; int ci = a;
#pragma unroll
                    for (int j = 0; j < TOPK; j++) {
                        if (cv > v[j] || (cv == v[j] && ci < id[j])) {
                            float tv = v[j]; v[j] = cv; cv = tv;
                            int ti = id[j]; id[j] = ci; ci = ti;
                        }
                    }
                }
            }
        }
    } else {
        for (int a = t; a < N; a += 128) {
            float2 an = anchors[a];
            if (an.x >= gt.x && an.x <= gt.z && an.y >= gt.y && an.y <= gt.w) {
                float4 pb = pb_b[a];
                float iou = iou_fn(pb, gt);
                float s = sc_b[a];
                float prob = 1.0f / (1.0f + expf(-s));
                float i2 = iou * iou;
                float align = prob * (i2 * i2 * i2);
                if (align > v[TOPK - 1]) {
                    float cv = align; int ci = a;
#pragma unroll
                    for (int j = 0; j < TOPK; j++) {
                        if (cv > v[j] || (cv == v[j] && ci < id[j])) {
                            float tv = v[j]; v[j] = cv; cv = tv;
                            int ti = id[j]; id[j] = ci; ci = ti;
                        }
                    }
                }
            }
        }
    }

    // block top-13 merge via per-thread sorted heads
    __shared__ float s_v[4]; __shared__ int s_i[4]; __shared__ int s_t[4];
    __shared__ int w_t; __shared__ int s_done;
    if (t == 0) s_done = 0;
    int ptr = 0;
    int lane = t & 31, wid = t >> 5;
    __syncthreads();

    for (int round = 0; round < TOPK; round++) {
        float hv = (ptr < TOPK) ? v[ptr] : -FLT_MAX;
        int   hi = (ptr < TOPK) ? id[ptr] : 0x7FFFFFFF;
        int   ht = t;
#pragma unroll
        for (int off = 16; off > 0; off >>= 1) {
            float ov = __shfl_down_sync(0xFFFFFFFFu, hv, off);
            int   oi = __shfl_down_sync(0xFFFFFFFFu, hi, off);
            int   ot = __shfl_down_sync(0xFFFFFFFFu, ht, off);
            if (ov > hv || (ov == hv && oi < hi)) { hv = ov; hi = oi; ht = ot; }
        }
        if (lane == 0) { s_v[wid] = hv; s_i[wid] = hi; s_t[wid] = ht; }
        __syncthreads();
        if (t == 0) {
            float bv = s_v[0]; int bi = s_i[0]; int bt = s_t[0];
            for (int w = 1; w < 4; w++) {
                if (s_v[w] > bv || (s_v[w] == bv && s_i[w] < bi)) {
                    bv = s_v[w]; bi = s_i[w]; bt = s_t[w];
                }
            }
            if (bv < 0.0f) {
                s_done = 1;
            } else {
                unsigned int bits = __float_as_uint(bv);
                unsigned long long key = (((unsigned long long)(bits + 1u)) << 32)
                                       | (unsigned long long)(0xFFFFFFFFu - (unsigned)g);
                atomicMax(&g_key[(size_t)b * N + bi], key);
                int pos = atomicAdd(&g_cnt, 1);
                if (pos < MAX_LIST) g_list[pos] = make_int2(b * N + bi, g);
            }
            w_t = bt;
        }
        __syncthreads();
        if (s_done) break;
        if (t == w_t) ptr++;
    }
}

// Foreground terms over the compacted selection list.
__global__ __launch_bounds__(256) void k_fg(
    const float4* __restrict__ pred_boxes, const float* __restrict__ scores,
    const float2* __restrict__ anchors, const float* __restrict__ strides,
    const float* __restrict__ logits, const float* __restrict__ prompt,
    const float4* __restrict__ gts, const int* __restrict__ img_p,
    int B, int N, int G, int P)
{
    __shared__ double s_acc[MAX_B * 8 > 512 ? 1 : MAX_B * 8];
    // per-block accumulation buffer sized B*8 (B<=64 -> 512 doubles = 4KB)
    extern __shared__ double dummy[];
    __shared__ double acc_s[512];
    int t = threadIdx.x;
    for (int i = t; i < B * 8; i += 256) acc_s[i] = 0.0;
    __syncthreads();

    int i = blockIdx.x * 256 + t;
    int cnt = g_cnt;
    if (i < cnt && i < MAX_LIST) {
        int2 e = g_list[i];
        int idx = e.x, g = e.y;
        int b = idx / N, a = idx - b * N;
        unsigned long long key = g_key[idx];
        int gw = (int)(0xFFFFFFFFu - (unsigned)(key & 0xFFFFFFFFull));
        if (gw == g) {
            float4 gt = gts[b * G + g];
            float4 pb = pred_boxes[idx];
            float s = scores[idx];
            float prob = 1.0f / (1.0f + expf(-s));
            float iou = iou_fn(pb, gt);
            float ts = fmaxf(iou, 0.1f);
            // CIoU
            float cw = fmaxf(pb.z, gt.z) - fminf(pb.x, gt.x);
            float ch = fmaxf(pb.w, gt.w) - fminf(pb.y, gt.y);
            float c2 = cw * cw + ch * ch + EPSF;
            float dx = gt.x + gt.z - pb.x - pb.z;
            float dy = gt.y + gt.w - pb.y - pb.w;
            float rho2 = (dx * dx + dy * dy) * 0.25f;
            float w1 = pb.z - pb.x, h1 = pb.w - pb.y + EPSF;
            float w2 = gt.z - gt.x, h2 = gt.w - gt.y + EPSF;
            float dat = atanf(w2 / h2) - atanf(w1 / h1);
            float vv = 0.40528473456935109f * dat * dat;
            float alpha = vv / (vv - iou + 1.0f + EPSF);
            float ciou = iou - rho2 / c2 - vv * alpha;
            // DFL
            float2 an = anchors[a];
            float st = strides[a];
            float dist[4];
            dist[0] = (an.x - gt.x) / st;
            dist[1] = (an.y - gt.y) / st;
            dist[2] = (gt.z - an.x) / st;
            dist[3] = (gt.w - an.y) / st;
            const float* lg = logits + (size_t)idx * 64;
            float dflv = 0.0f;
#pragma unroll
            for (int ch_i = 0; ch_i < 4; ch_i++) {
                float x[16];
                const float4* l4 = (const float4*)(lg + ch_i * 16);
#pragma unroll
                for (int q = 0; q < 4; q++) {
                    float4 f = l4[q];
                    x[q * 4 + 0] = f.x; x[q * 4 + 1] = f.y;
                    x[q * 4 + 2] = f.z; x[q * 4 + 3] = f.w;
                }
                float m = x[0];
#pragma unroll
                for (int q = 1; q < 16; q++) m = fmaxf(m, x[q]);
                float se = 0.0f;
#pragma unroll
                for (int q = 0; q < 16; q++) se += expf(x[q] - m);
                float logZ = m + logf(se);
                float d = fminf(fmaxf(dist[ch_i], 0.0f), 16.0f - 1.0f - 0.01f);
                int tl = (int)d;
                int tr = min(tl + 1, 15);
                float wl = (float)tr - d;
                float wr = 1.0f - wl;
                dflv += (logZ - x[tl]) * wl + (logZ - x[tr]) * wr;
            }
            // contrast
            float img = fmaxf((float)img_p[0], 1.0f);
            float cx = (gt.x + gt.z) * 0.5f / img;
            float cy = (gt.y + gt.w) * 0.5f / img;
            float cn = fmaxf(sqrtf(cx * cx + cy * cy), 1e-12f);
            cx /= cn; cy /= cn;
            float p0 = prompt[(size_t)b * P + 0], p1 = prompt[(size_t)b * P + 1];
            float pn = fmaxf(sqrtf(p0 * p0 + p1 * p1), 1e-12f);
            float ctr = 1.0f - (cx * p0 + cy * p1) / pn;

            double* A = acc_s + b * 8;
            atomicAdd(&A[0], (double)(-s * ts));      // BCE correction
            atomicAdd(&A[1], 1.0);                    // n_pos
            atomicAdd(&A[2], (double)prob);           // pos prob
            atomicAdd(&A[4], (double)iou);            // matched iou
            atomicAdd(&A[5], (double)(1.0f - ciou));  // iou loss
            atomicAdd(&A[6], (double)dflv);           // dfl
            atomicAdd(&A[7], (double)ctr);            // contrast
        }
    }
    __syncthreads();
    for (int j = t; j < B * 8; j += 256) {
        double val = acc_s[j];
        if (val != 0.0) atomicAdd(&g_acc[j], val);
    }
}

// Finalize + cleanup (keys, counter, accumulators) for graph determinism.
__global__ __launch_bounds__(256) void k_final(float* __restrict__ out, int B, int N) {
    int t = threadIdx.x;
    int cnt = g_cnt;
    if (cnt > MAX_LIST) cnt = MAX_LIST;
    for (int i = t; i < cnt; i += 256) g_key[g_list[i].x] = 0ULL;

    __shared__ double pm[MAX_B], pi[MAX_B], pdf[MAX_B], pc[MAX_B];
    __shared__ double pt[MAX_B], pp[MAX_B], ptot[MAX_B], pmi[MAX_B];
    if (t < B) {
        const double* A = &g_acc[t * 8];
        double np = A[1];
        double den = fmax(np, 1.0);
        pm[t] = A[0] / (double)N;
        pt[t] = np;
        pp[t] = A[2];
        ptot[t] = A[3];
        pmi[t] = A[4];
        pi[t] = A[5] / den;
        pdf[t] = A[6] / (4.0 * den);
        pc[t] = A[7] / den;
    }
    __syncthreads();
    if (t == 0) {
        double match = 0, iou = 0, dfl = 0, ctr = 0, tp = 0, pos = 0, tot = 0, mi = 0;
        for (int b = 0; b < B; b++) {
            match += pm[b]; iou += pi[b]; dfl += pdf[b]; ctr += pc[b];
            tp += pt[b]; pos += pp[b]; tot += ptot[b]; mi += pmi[b];
        }
        double nb = (double)B;
        double tneg = (double)B * (double)N - tp;
        out[0] = (float)((1.0 * match + 7.5 * iou + 1.5 * dfl + 1.0 * ctr) / nb);
        out[1] = (float)(match / nb);
        out[2] = (float)(iou / nb);
        out[3] = (float)(dfl / nb);
        out[4] = (float)(ctr / nb);
        out[5] = (float)tp;
        out[6] = (float)tneg;
        out[7] = (float)(pos / fmax(tp, 1.0));
        out[8] = (float)((tot - pos) / fmax(tneg, 1.0));
        out[9] = (float)(mi / fmax(tp, 1.0));
        g_cnt = 0;
    }
    __syncthreads();
    for (int j = t; j < B * 8; j += 256) g_acc[j] = 0.0;
}

extern "C" void kernel_launch(void* const* d_in, const int* in_sizes, int n_in,
                              void* d_out, int out_size) {
    const float* pred_boxes = (const float*)d_in[0];
    const float* pred_scores = (const float*)d_in[1];
    const float* anchors = (const float*)d_in[2];
    const float* strides = (const float*)d_in[3];
    const float* logits = (const float*)d_in[4];
    const float* prompt = (const float*)d_in[5];
    const float* gts = (const float*)d_in[6];
    const int* imgp = (const int*)d_in[7];

    int N = in_sizes[2] / 2;
    int B = in_sizes[1] / N;
    int G = in_sizes[6] / (4 * B);
    int P = in_sizes[5] / B;

    dim3 gs((N + 1023) / 1024, (unsigned)B);
    k_score<<<gs, 256>>>(pred_scores, B, N);
    k_assign<<<B * G, 128>>>((const float4*)pred_boxes, pred_scores,
                             (const float2*)anchors, (const float4*)gts, imgp, B, N, G);
    int cap = B * G * TOPK;
    k_fg<<<(cap + 255) / 256, 256>>>((const float4*)pred_boxes, pred_scores,
                                     (const float2*)anchors, strides, logits, prompt,
                                     (const float4*)gts, imgp, B, N, G, P);
    k_final<<<1, 256>>>((float*)d_out, B, N);
}

// round 3
// speedup vs baseline: 1.8647x; 1.1200x over previous
#include <cuda_runtime.h>
#include <math.h>

#define TOPK 13
#define EPSF 1e-7f
#define MAX_BN (1 << 20)
#define MAX_B 64
#define MAX_LIST 16384
#define FINAL_BLOCKS 16

typedef unsigned long long u64;

__device__ u64 g_key[MAX_BN];
__device__ double g_acc[MAX_B * 8];
__device__ int g_cnt;
__device__ int g_cnt2;
__device__ int2 g_list[MAX_LIST];

__device__ __forceinline__ float iou_fn(float4 a, float4 b) {
    float x1 = fmaxf(a.x, b.x), y1 = fmaxf(a.y, b.y);
    float x2 = fminf(a.z, b.z), y2 = fminf(a.w, b.w);
    float inter = fmaxf(x2 - x1, 0.0f) * fmaxf(y2 - y1, 0.0f);
    float aa = (a.z - a.x) * (a.w - a.y);
    float ab = (b.z - b.x) * (b.w - b.y);
    return inter / (aa + ab - inter + EPSF);
}

// Fused kernel: blocks [0, BG) do assignment (one per image,gt);
// blocks [BG, BG+scoreBlocks) do the dense score reduction.
__global__ __launch_bounds__(256) void k_main(
    const float4* __restrict__ pred_boxes, const float* __restrict__ scores,
    const float2* __restrict__ anchors, const float4* __restrict__ gts,
    const int* __restrict__ img_p, int B, int N, int G, int BG, int total)
{
    int t = threadIdx.x;

    if ((int)blockIdx.x >= BG) {
        // ---------------- score role: flat over B*N ----------------
        int sb = blockIdx.x - BG;
        int i0 = (sb * 256 + t) * 8;
        float bce = 0.0f, ps = 0.0f;
#pragma unroll
        for (int q = 0; q < 2; q++) {
            int base = i0 + q * 4;
            float sv[4];
            bool full = (base + 3 < total);
            if (full) {
                float4 s4 = *(const float4*)(scores + base);
                sv[0] = s4.x; sv[1] = s4.y; sv[2] = s4.z; sv[3] = s4.w;
            }
#pragma unroll
            for (int j = 0; j < 4; j++) {
                float s;
                bool valid = full;
                if (full) s = sv[j];
                else { int i = base + j; valid = (i < total); s = valid ? scores[i] : 0.0f; }
                if (valid) {
                    float e = __expf(-fabsf(s));
                    float pa = 1.0f / (1.0f + e);         // sigmoid(|s|)
                    bce += fmaxf(s, 0.0f) - __logf(pa);    // max(s,0)+log1p(e^-|s|)
                    ps += (s >= 0.0f) ? pa : 1.0f - pa;
                }
            }
        }
        __shared__ float r0[8], r1[8];
        int lane = t & 31, wid = t >> 5;
#pragma unroll
        for (int off = 16; off > 0; off >>= 1) {
            bce += __shfl_down_sync(0xFFFFFFFFu, bce, off);
            ps  += __shfl_down_sync(0xFFFFFFFFu, ps, off);
        }
        if (lane == 0) { r0[wid] = bce; r1[wid] = ps; }
        __syncthreads();
        if (t == 0) {
            float a = 0.0f, p = 0.0f;
            for (int w = 0; w < 8; w++) { a += r0[w]; p += r1[w]; }
            atomicAdd(&g_acc[0], (double)a);   // global bce0 (slot b=0, q=0)
            atomicAdd(&g_acc[3], (double)p);   // global prob sum (slot b=0, q=3)
        }
        return;
    }

    // ---------------- assign role ----------------
    int bg = blockIdx.x;
    int b = bg / G, g = bg % G;
    float4 gt = gts[bg];

    u64 v[TOPK];
#pragma unroll
    for (int j = 0; j < TOPK; j++) v[j] = 0ULL;

    const float4* pb_b = pred_boxes + (size_t)b * N;
    const float*  sc_b = scores + (size_t)b * N;

    int img = img_p[0];
    int n0 = img / 8, n1 = img / 16, n2 = img / 32;
    bool structured = (n0 * n0 + n1 * n1 + n2 * n2 == N) && img > 0;

    if (structured) {
        int nn[3] = {n0, n1, n2};
        int base[3] = {0, n0 * n0, n0 * n0 + n1 * n1};
        int c0[3], r0a[3], cw[3], m[3];
        int M = 0;
#pragma unroll
        for (int sc = 0; sc < 3; sc++) {
            float s = (float)(8 << sc);
            int n = nn[sc];
            int cl = (int)floorf(gt.x / s - 0.5f) - 1;
            int ch = (int)ceilf(gt.z / s - 0.5f) + 1;
            int rl = (int)floorf(gt.y / s - 0.5f) - 1;
            int rh = (int)ceilf(gt.w / s - 0.5f) + 1;
            cl = max(cl, 0); ch = min(ch, n - 1);
            rl = max(rl, 0); rh = min(rh, n - 1);
            int ccw = ch - cl + 1, crh = rh - rl + 1;
            if (ccw < 0) ccw = 0;
            if (crh < 0) crh = 0;
            c0[sc] = cl; r0a[sc] = rl; cw[sc] = ccw;
            m[sc] = ccw * crh;
            M += m[sc];
        }
        for (int k = t; k < M; k += 256) {
            int sc = 0, rel = k;
            while (rel >= m[sc]) { rel -= m[sc]; sc++; }
            int row = rel / cw[sc] + r0a[sc];
            int col = rel % cw[sc] + c0[sc];
            int a = base[sc] + row * nn[sc] + col;
            float2 an = anchors[a];
            if (an.x >= gt.x && an.x <= gt.z && an.y >= gt.y && an.y <= gt.w) {
                float4 pb = pb_b[a];
                float iou = iou_fn(pb, gt);
                float s = sc_b[a];
                float prob = 1.0f / (1.0f + __expf(-s));
                float i2 = iou * iou;
                float align = prob * (i2 * i2 * i2);
                u64 key = ((u64)__float_as_uint(align) << 32)
                        | (u64)(0xFFFFFFFFu - (unsigned)a);
                if (key > v[TOPK - 1]) {
#pragma unroll
                    for (int j = 0; j < TOPK; j++) {
                        if (key > v[j]) { u64 tv = v[j]; v[j] = key; key = tv; }
                    }
                }
            }
        }
    } else {
        for (int a = t; a < N; a += 256) {
            float2 an = anchors[a];
            if (an.x >= gt.x && an.x <= gt.z && an.y >= gt.y && an.y <= gt.w) {
                float4 pb = pb_b[a];
                float iou = iou_fn(pb, gt);
                float s = sc_b[a];
                float prob = 1.0f / (1.0f + __expf(-s));
                float i2 = iou * iou;
                float align = prob * (i2 * i2 * i2);
                u64 key = ((u64)__float_as_uint(align) << 32)
                        | (u64)(0xFFFFFFFFu - (unsigned)a);
                if (key > v[TOPK - 1]) {
#pragma unroll
                    for (int j = 0; j < TOPK; j++) {
                        if (key > v[j]) { u64 tv = v[j]; v[j] = key; key = tv; }
                    }
                }
            }
        }
    }

    // block-wide top-13 merge (head-pointer rounds on packed u64)
    __shared__ u64 s_v[8]; __shared__ int s_t[8];
    __shared__ u64 s_w[TOPK];
    __shared__ int w_t; __shared__ int s_done;
    if (t == 0) s_done = 0;
    if (t < TOPK) s_w[t] = 0ULL;
    int ptr = 0;
    int lane = t & 31, wid = t >> 5;
    __syncthreads();

    for (int round = 0; round < TOPK; round++) {
        u64 hv = (ptr < TOPK) ? v[ptr] : 0ULL;
        int ht = t;
#pragma unroll
        for (int off = 16; off > 0; off >>= 1) {
            u64 ov = __shfl_down_sync(0xFFFFFFFFu, hv, off);
            int ot = __shfl_down_sync(0xFFFFFFFFu, ht, off);
            if (ov > hv) { hv = ov; ht = ot; }
        }
        if (lane == 0) { s_v[wid] = hv; s_t[wid] = ht; }
        __syncthreads();
        if (t == 0) {
            u64 bv = s_v[0]; int bt = s_t[0];
            for (int w = 1; w < 8; w++)
                if (s_v[w] > bv) { bv = s_v[w]; bt = s_t[w]; }
            if (bv == 0ULL) s_done = 1;
            else { s_w[round] = bv; w_t = bt; }
        }
        __syncthreads();
        if (s_done) break;
        if (t == w_t) ptr++;
    }
    __syncthreads();

    if (t < TOPK) {
        u64 w = s_w[t];
        if (w != 0ULL) {
            unsigned bits = (unsigned)(w >> 32);
            int a = (int)(0xFFFFFFFFu - (unsigned)(w & 0xFFFFFFFFull));
            u64 key = ((u64)(bits + 1u) << 32)
                    | (u64)(0xFFFFFFFFu - (unsigned)g);
            atomicMax(&g_key[(size_t)b * N + a], key);
            int pos = atomicAdd(&g_cnt, 1);
            if (pos < MAX_LIST) g_list[pos] = make_int2(b * N + a, g);
        }
    }
}

// Foreground terms over the compacted selection list.
__global__ __launch_bounds__(256) void k_fg(
    const float4* __restrict__ pred_boxes, const float* __restrict__ scores,
    const float2* __restrict__ anchors, const float* __restrict__ strides,
    const float* __restrict__ logits, const float* __restrict__ prompt,
    const float4* __restrict__ gts, const int* __restrict__ img_p,
    int B, int N, int G, int P)
{
    __shared__ double acc_s[MAX_B * 8];
    int t = threadIdx.x;
    if (blockIdx.x == 0 && t == 0) {
        int c = g_cnt;
        g_cnt2 = c < MAX_LIST ? c : MAX_LIST;
    }
    for (int i = t; i < B * 8; i += 256) acc_s[i] = 0.0;
    __syncthreads();

    int i = blockIdx.x * 256 + t;
    int cnt = g_cnt;
    if (i < cnt && i < MAX_LIST) {
        int2 e = g_list[i];
        int idx = e.x, g = e.y;
        int b = idx / N, a = idx - b * N;
        u64 key = g_key[idx];
        int gw = (int)(0xFFFFFFFFu - (unsigned)(key & 0xFFFFFFFFull));
        if (gw == g) {
            float4 gt = gts[b * G + g];
            float4 pb = pred_boxes[idx];
            float s = scores[idx];
            float prob = 1.0f / (1.0f + expf(-s));
            float iou = iou_fn(pb, gt);
            float ts = fmaxf(iou, 0.1f);
            float cw = fmaxf(pb.z, gt.z) - fminf(pb.x, gt.x);
            float ch = fmaxf(pb.w, gt.w) - fminf(pb.y, gt.y);
            float c2 = cw * cw + ch * ch + EPSF;
            float dx = gt.x + gt.z - pb.x - pb.z;
            float dy = gt.y + gt.w - pb.y - pb.w;
            float rho2 = (dx * dx + dy * dy) * 0.25f;
            float w1 = pb.z - pb.x, h1 = pb.w - pb.y + EPSF;
            float w2 = gt.z - gt.x, h2 = gt.w - gt.y + EPSF;
            float dat = atanf(w2 / h2) - atanf(w1 / h1);
            float vv = 0.40528473456935109f * dat * dat;
            float alpha = vv / (vv - iou + 1.0f + EPSF);
            float ciou = iou - rho2 / c2 - vv * alpha;
            float2 an = anchors[a];
            float st = strides[a];
            float dist[4];
            dist[0] = (an.x - gt.x) / st;
            dist[1] = (an.y - gt.y) / st;
            dist[2] = (gt.z - an.x) / st;
            dist[3] = (gt.w - an.y) / st;
            const float* lg = logits + (size_t)idx * 64;
            float dflv = 0.0f;
#pragma unroll
            for (int ch_i = 0; ch_i < 4; ch_i++) {
                float x[16];
                const float4* l4 = (const float4*)(lg + ch_i * 16);
#pragma unroll
                for (int q = 0; q < 4; q++) {
                    float4 f = l4[q];
                    x[q * 4 + 0] = f.x; x[q * 4 + 1] = f.y;
                    x[q * 4 + 2] = f.z; x[q * 4 + 3] = f.w;
                }
                float m = x[0];
#pragma unroll
                for (int q = 1; q < 16; q++) m = fmaxf(m, x[q]);
                float se = 0.0f;
#pragma unroll
                for (int q = 0; q < 16; q++) se += expf(x[q] - m);
                float logZ = m + logf(se);
                float d = fminf(fmaxf(dist[ch_i], 0.0f), 16.0f - 1.0f - 0.01f);
                int tl = (int)d;
                int tr = min(tl + 1, 15);
                float wl = (float)tr - d;
                float wr = 1.0f - wl;
                dflv += (logZ - x[tl]) * wl + (logZ - x[tr]) * wr;
            }
            float img = fmaxf((float)img_p[0], 1.0f);
            float cx = (gt.x + gt.z) * 0.5f / img;
            float cy = (gt.y + gt.w) * 0.5f / img;
            float cn = fmaxf(sqrtf(cx * cx + cy * cy), 1e-12f);
            cx /= cn; cy /= cn;
            float p0 = prompt[(size_t)b * P + 0], p1 = prompt[(size_t)b * P + 1];
            float pn = fmaxf(sqrtf(p0 * p0 + p1 * p1), 1e-12f);
            float ctr = 1.0f - (cx * p0 + cy * p1) / pn;

            double* A = acc_s + b * 8;
            atomicAdd(&A[0], (double)(-s * ts));
            atomicAdd(&A[1], 1.0);
            atomicAdd(&A[2], (double)prob);
            atomicAdd(&A[4], (double)iou);
            atomicAdd(&A[5], (double)(1.0f - ciou));
            atomicAdd(&A[6], (double)dflv);
            atomicAdd(&A[7], (double)ctr);
        }
    }
    __syncthreads();
    for (int j = t; j < B * 8; j += 256) {
        double val = acc_s[j];
        if (val != 0.0) atomicAdd(&g_acc[j], val);
    }
}

// Multi-block: cleanup keys (all blocks, via g_cnt2 snapshot); block 0 finalizes.
__global__ __launch_bounds__(256) void k_final(float* __restrict__ out, int B, int N) {
    int t = threadIdx.x;
    int cnt = g_cnt2;
    if (cnt > MAX_LIST) cnt = MAX_LIST;
    for (int i = blockIdx.x * 256 + t; i < cnt; i += FINAL_BLOCKS * 256)
        g_key[g_list[i].x] = 0ULL;
    if (blockIdx.x != 0) return;

    __shared__ double pm[MAX_B], pi[MAX_B], pdf[MAX_B], pc[MAX_B];
    __shared__ double pt[MAX_B], pp[MAX_B], ptot[MAX_B], pmi[MAX_B];
    if (t < B) {
        const double* A = &g_acc[t * 8];
        double np = A[1];
        double den = fmax(np, 1.0);
        pm[t] = A[0] / (double)N;
        pt[t] = np;
        pp[t] = A[2];
        ptot[t] = A[3];
        pmi[t] = A[4];
        pi[t] = A[5] / den;
        pdf[t] = A[6] / (4.0 * den);
        pc[t] = A[7] / den;
    }
    __syncthreads();
    if (t == 0) {
        double match = 0, iou = 0, dfl = 0, ctr = 0, tp = 0, pos = 0, tot = 0, mi = 0;
        for (int b = 0; b < B; b++) {
            match += pm[b]; iou += pi[b]; dfl += pdf[b]; ctr += pc[b];
            tp += pt[b]; pos += pp[b]; tot += ptot[b]; mi += pmi[b];
        }
        double nb = (double)B;
        double tneg = (double)B * (double)N - tp;
        out[0] = (float)((1.0 * match + 7.5 * iou + 1.5 * dfl + 1.0 * ctr) / nb);
        out[1] = (float)(match / nb);
        out[2] = (float)(iou / nb);
        out[3] = (float)(dfl / nb);
        out[4] = (float)(ctr / nb);
        out[5] = (float)tp;
        out[6] = (float)tneg;
        out[7] = (float)(pos / fmax(tp, 1.0));
        out[8] = (float)((tot - pos) / fmax(tneg, 1.0));
        out[9] = (float)(mi / fmax(tp, 1.0));
        g_cnt = 0;
    }
    __syncthreads();
    for (int j = t; j < B * 8; j += 256) g_acc[j] = 0.0;
}

extern "C" void kernel_launch(void* const* d_in, const int* in_sizes, int n_in,
                              void* d_out, int out_size) {
    const float* pred_boxes = (const float*)d_in[0];
    const float* pred_scores = (const float*)d_in[1];
    const float* anchors = (const float*)d_in[2];
    const float* strides = (const float*)d_in[3];
    const float* logits = (const float*)d_in[4];
    const float* prompt = (const float*)d_in[5];
    const float* gts = (const float*)d_in[6];
    const int* imgp = (const int*)d_in[7];

    int N = in_sizes[2] / 2;
    int B = in_sizes[1] / N;
    int G = in_sizes[6] / (4 * B);
    int P = in_sizes[5] / B;
    int BG = B * G;
    int total = B * N;
    int scoreBlocks = (total + 2047) / 2048;

    k_main<<<BG + scoreBlocks, 256>>>((const float4*)pred_boxes, pred_scores,
                                      (const float2*)anchors, (const float4*)gts,
                                      imgp, B, N, G, BG, total);
    int cap = BG * TOPK;
    k_fg<<<(cap + 255) / 256, 256>>>((const float4*)pred_boxes, pred_scores,
                                     (const float2*)anchors, strides, logits, prompt,
                                     (const float4*)gts, imgp, B, N, G, P);
    k_final<<<FINAL_BLOCKS, 256>>>((float*)d_out, B, N);
}